// round 11
// baseline (speedup 1.0000x reference)
#include <cuda_runtime.h>
#include <cstdint>

#define SEQ 4096
#define HD 32
#define NH 8
#define BATCH 2

// Scratch (static device globals: allowed; no runtime allocation)
// g_q: [bh][n][d]          pre-scaled by 1/sqrt(32)*log2(e), tf32-rounded
// g_k: [bh][n][perm(d)]    pair-permuted for LDS.64 B-frags, tf32-rounded
// g_v: [bh][n/2][d][n&1]   row-pair interleaved, tf32-rounded
__device__ float g_q[BATCH*NH*SEQ*HD];
__device__ float g_k[BATCH*NH*SEQ*HD];
__device__ float g_v[BATCH*NH*SEQ*HD];
__device__ float g_o[BATCH*SEQ*NH*HD];   // [b][n][h*32+d]
// Pair-packed tf32 weights: Wp[((a*4+b)*N + c)*2 + i] = tf32(W[8a+b+4i][c])
__device__ float g_wqkv_p[256*768];
__device__ float g_wproj_p[256*256];

__device__ __forceinline__ float to_tf32(float x){
    uint32_t r; asm("cvt.rna.tf32.f32 %0, %1;" : "=r"(r) : "f"(x));
    return __uint_as_float(r);
}
__device__ __forceinline__ float ex2(float x){
    float y; asm("ex2.approx.f32 %0, %1;" : "=f"(y) : "f"(x)); return y;
}
__device__ __forceinline__ uint32_t fu(float x){ return __float_as_uint(x); }

__device__ __forceinline__ void mma8(float* c, const uint32_t* a, const uint32_t* b){
    asm volatile("mma.sync.aligned.m16n8k8.row.col.f32.tf32.tf32.f32 "
        "{%0,%1,%2,%3}, {%4,%5,%6,%7}, {%8,%9}, {%0,%1,%2,%3};\n"
        : "+f"(c[0]), "+f"(c[1]), "+f"(c[2]), "+f"(c[3])
        : "r"(a[0]), "r"(a[1]), "r"(a[2]), "r"(a[3]), "r"(b[0]), "r"(b[1]));
}
__device__ __forceinline__ float4 cvt4(float4 v){
    v.x = to_tf32(v.x); v.y = to_tf32(v.y); v.z = to_tf32(v.z); v.w = to_tf32(v.w);
    return v;
}

#define ATT_SCALE (0.17677669529663687f * 1.4426950408889634f)  // 1/sqrt(32)*log2(e)

// ---------------------------------------------------------------------------
// Weight pre-pack: Wp[a][b][c][i] = tf32(W[8a+b+4i][c])   (one-shot per call)
// ---------------------------------------------------------------------------
__global__ void pack_w_kernel(const float* __restrict__ Wq,
                              const float* __restrict__ Wj)
{
    int idx = blockIdx.x * blockDim.x + threadIdx.x;
    const int NQ = 256*768;
    if (idx < NQ) {
        int i = idx & 1;
        int c = (idx >> 1) % 768;
        int ab = (idx >> 1) / 768;
        int a = ab >> 2, b = ab & 3;
        g_wqkv_p[idx] = to_tf32(Wq[(size_t)(8*a + b + 4*i)*768 + c]);
    } else {
        int e = idx - NQ;
        if (e < 256*256) {
            int i = e & 1;
            int c = (e >> 1) % 256;
            int ab = (e >> 1) / 256;
            int a = ab >> 2, b = ab & 3;
            g_wproj_p[e] = to_tf32(Wj[(size_t)(8*a + b + 4*i)*256 + c]);
        }
    }
}

// ---------------------------------------------------------------------------
// tf32 GEMM with pair-packed B.  MODE 0: scatter packed q/k/v.  MODE 1: ->Out.
// BM=BN=64, BK=32, 128 threads (2x2 warps of 32x32).
// B path: global Wp -> smem = raw f4 copy (no cvt); B-frag = single LDS.64.
// Bsp row stride 136 floats: STS.128 phases and LDS.64 both conflict-free.
// ---------------------------------------------------------------------------
template<int MODE>
__global__ __launch_bounds__(128) void gemm_kernel(
    const float* __restrict__ Ain, const float* __restrict__ bias,
    float* __restrict__ Out, int M, int Nout, int K)
{
    __shared__ float As[64][36];
    __shared__ float Bsp[16][136];   // rows (a_off*4+b), 64 f2 pairs + pad

    const float* A  = (MODE == 1) ? (const float*)g_o : Ain;
    const float* Wp = (MODE == 1) ? g_wproj_p : g_wqkv_p;

    int tid = threadIdx.x;
    int warp = tid >> 5, lane = tid & 31;
    int wm = warp >> 1, wn = warp & 1;
    int g = lane >> 2, tg = lane & 3;
    int row0 = blockIdx.y * 64, col0 = blockIdx.x * 64;

    float acc[2][4][4];
#pragma unroll
    for (int i = 0; i < 2; i++)
#pragma unroll
        for (int j = 0; j < 4; j++)
#pragma unroll
            for (int r = 0; r < 4; r++) acc[i][j][r] = 0.f;

    int ar = tid >> 3, ac = (tid & 7) * 4;   // A loader
    int br = tid >> 3, bl = tid & 7;         // B loader: row br (=a_off*4+b), f4 lane bl

    // global base for B row br of the k0 block (a0 = k0>>3):
    //   Wp + (((a0 + (br>>2))*4 + (br&3))*Nout + col0)*2  + (bl + i*8)*4
    float4 ra[4], rb[4];
#pragma unroll
    for (int i = 0; i < 4; i++) {
        ra[i] = *(const float4*)(A + (size_t)(row0 + ar + i*16) * K + ac);
        rb[i] = *(const float4*)(Wp
                + ((size_t)((0 + (br >> 2))*4 + (br & 3)) * Nout + col0) * 2
                + (bl + i*8) * 4);
    }

    for (int k0 = 0; k0 < K; k0 += 32) {
#pragma unroll
        for (int i = 0; i < 4; i++) {
            *(float4*)&As[ar + i*16][ac] = cvt4(ra[i]);
            *(float4*)&Bsp[br][(bl + i*8)*4] = rb[i];   // raw copy, pre-rounded
        }
        __syncthreads();

        if (k0 + 32 < K) {
            int a0 = (k0 + 32) >> 3;
#pragma unroll
            for (int i = 0; i < 4; i++) {
                ra[i] = *(const float4*)(A + (size_t)(row0 + ar + i*16) * K + k0 + 32 + ac);
                rb[i] = *(const float4*)(Wp
                        + ((size_t)((a0 + (br >> 2))*4 + (br & 3)) * Nout + col0) * 2
                        + (bl + i*8) * 4);
            }
        }

#pragma unroll
        for (int kk = 0; kk < 32; kk += 8) {
            int prow = (kk >> 3)*4 + tg;
            uint32_t af[2][4], bf[4][2];
#pragma unroll
            for (int mt = 0; mt < 2; mt++) {
                int r = wm*32 + mt*16;
                af[mt][0] = fu(As[r + g    ][kk + tg    ]);
                af[mt][1] = fu(As[r + g + 8][kk + tg    ]);
                af[mt][2] = fu(As[r + g    ][kk + tg + 4]);
                af[mt][3] = fu(As[r + g + 8][kk + tg + 4]);
            }
#pragma unroll
            for (int nt = 0; nt < 4; nt++) {
                float2 p = *(const float2*)&Bsp[prow][(wn*32 + nt*8 + g)*2];
                bf[nt][0] = fu(p.x);
                bf[nt][1] = fu(p.y);
            }
#pragma unroll
            for (int mt = 0; mt < 2; mt++)
#pragma unroll
                for (int nt = 0; nt < 4; nt++)
                    mma8(acc[mt][nt], af[mt], bf[nt]);
        }
        __syncthreads();
    }

#pragma unroll
    for (int mt = 0; mt < 2; mt++) {
#pragma unroll
        for (int nt = 0; nt < 4; nt++) {
#pragma unroll
            for (int rr = 0; rr < 4; rr++) {
                int r = row0 + wm*32 + mt*16 + g + ((rr >= 2) ? 8 : 0);
                int c = col0 + wn*32 + nt*8 + 2*tg + (rr & 1);
                float val = acc[mt][nt][rr] + bias[c];
                if (MODE == 0) {
                    int which = c >> 8, head = (c >> 5) & 7, d = c & 31;
                    int b = r >> 12, n = r & 4095;
                    int bh = b*8 + head;
                    if (which == 0) {
                        g_q[((size_t)bh*SEQ + n)*HD + d] = to_tf32(val * ATT_SCALE);
                    } else if (which == 1) {
                        int p = ((d >> 3) << 3) + 2*(d & 3) + ((d >> 2) & 1);
                        g_k[((size_t)bh*SEQ + n)*HD + p] = to_tf32(val);
                    } else {
                        g_v[(size_t)bh*SEQ*HD + (size_t)(n >> 1)*64 + 2*d + (n & 1)]
                            = to_tf32(val);
                    }
                } else {
                    Out[(size_t)r * 256 + c] = val;
                }
            }
        }
    }
}

// ---------------------------------------------------------------------------
// Flash attention v5 (occ 4): BM=128, 128 threads = 4 warps x 32 rows (mt=2).
// Pre-packed q/k/v from gemm<0>; double-buffered Kp/Vp; one barrier per tile;
// fixed-reference softmax; per-j QK->ex2->PV pipeline; raw-bits P.
// ---------------------------------------------------------------------------
__global__ __launch_bounds__(128, 4) void attn_kernel()
{
    __shared__ union SM {
        float Qs[128][36];                                  // phase 1 only
        struct { float Kp[2][64][40]; float Vp[2][32][72]; } kv;  // mainloop
    } sm;

    int tid = threadIdx.x, warp = tid >> 5, lane = tid & 31;
    int g = lane >> 2, tg = lane & 3;
    int bh = blockIdx.y;
    const float* qb = g_q + (size_t)bh * SEQ * HD;
    const float* kb = g_k + (size_t)bh * SEQ * HD;
    const float* vb = g_v + (size_t)bh * SEQ * HD;   // pair-interleaved rows of 64
    int q0 = blockIdx.x * 128;

    int lrK = tid >> 3, acK = (tid & 7) * 4;    // K loader: 16 rows/pass, f4 cols
    int lrV = tid >> 4, acV = (tid & 15) * 4;   // V loader: 8 pair-rows/pass

    // ---- phase 1: Q load (already scaled+rounded) + fragment hoist ----
#pragma unroll
    for (int p = 0; p < 8; p++) {
        int row = p*16 + lrK;
        *(float4*)&sm.Qs[row][acK] =
            *(const float4*)(qb + (size_t)(q0 + row) * HD + acK);
    }
    __syncthreads();

    uint32_t qf[2][4][4];
#pragma unroll
    for (int mt = 0; mt < 2; mt++) {
        int r = warp*32 + mt*16;
#pragma unroll
        for (int k4 = 0; k4 < 4; k4++) {
            int kk = k4 * 8;
            qf[mt][k4][0] = fu(sm.Qs[r + g    ][kk + tg    ]);
            qf[mt][k4][1] = fu(sm.Qs[r + g + 8][kk + tg    ]);
            qf[mt][k4][2] = fu(sm.Qs[r + g    ][kk + tg + 4]);
            qf[mt][k4][3] = fu(sm.Qs[r + g + 8][kk + tg + 4]);
        }
    }
    __syncthreads();   // all hoists done before union reused as Kp/Vp

    float l_i[2][2] = {{0.f, 0.f}, {0.f, 0.f}};
    float o[2][4][4];
#pragma unroll
    for (int mt = 0; mt < 2; mt++)
#pragma unroll
        for (int j = 0; j < 4; j++)
#pragma unroll
            for (int r = 0; r < 4; r++) o[mt][j][r] = 0.f;

    // ---- tile 0: load + publish into buffer 0 ----
    float4 pk[4], pv[4];
#pragma unroll
    for (int p = 0; p < 4; p++) {
        pk[p] = *(const float4*)(kb + (size_t)(p*16 + lrK) * HD + acK);
        pv[p] = *(const float4*)(vb + (size_t)(p*8 + lrV) * 64 + acV);
    }
#pragma unroll
    for (int p = 0; p < 4; p++) {
        *(float4*)&sm.kv.Kp[0][p*16 + lrK][acK] = pk[p];
        *(float4*)&sm.kv.Vp[0][p*8 + lrV][acV] = pv[p];
    }
    __syncthreads();

    const int NT = SEQ / 64;
    for (int t = 0; t < NT; t++) {
        int cur = t & 1;

        if (t + 1 < NT) {
            int kv = (t + 1) * 64;
#pragma unroll
            for (int p = 0; p < 4; p++) {
                pk[p] = *(const float4*)(kb + (size_t)(kv + p*16 + lrK) * HD + acK);
                pv[p] = *(const float4*)(vb + (size_t)((kv >> 1) + p*8 + lrV) * 64 + acV);
            }
        }

        // ---- per-j pipeline: QK(j) -> ex2(j) -> PV(j) on buffer cur ----
#pragma unroll
        for (int j = 0; j < 8; j++) {
            float s0[4] = {0.f,0.f,0.f,0.f};
            float s1[4] = {0.f,0.f,0.f,0.f};
#pragma unroll
            for (int k4 = 0; k4 < 4; k4++) {
                float2 kpair = *(const float2*)&sm.kv.Kp[cur][j*8 + g][(k4*4 + tg)*2];
                uint32_t bf[2] = { fu(kpair.x), fu(kpair.y) };
                mma8(s0, qf[0][k4], bf);
                mma8(s1, qf[1][k4], bf);
            }
#pragma unroll
            for (int r = 0; r < 4; r++) { s0[r] = ex2(s0[r]); s1[r] = ex2(s1[r]); }
            l_i[0][0] += s0[0] + s0[1];
            l_i[0][1] += s0[2] + s0[3];
            l_i[1][0] += s1[0] + s1[1];
            l_i[1][1] += s1[2] + s1[3];

            uint32_t af0[4] = { fu(s0[0]), fu(s0[2]), fu(s0[1]), fu(s0[3]) };
            uint32_t af1[4] = { fu(s1[0]), fu(s1[2]), fu(s1[1]), fu(s1[3]) };
#pragma unroll
            for (int ntd = 0; ntd < 4; ntd++) {
                float2 vpair = *(const float2*)&sm.kv.Vp[cur][4*j + tg][(ntd*8 + g)*2];
                uint32_t bf[2] = { fu(vpair.x), fu(vpair.y) };
                mma8(o[0][ntd], af0, bf);
                mma8(o[1][ntd], af1, bf);
            }
        }

        // ---- publish tile t+1 into the other buffer (overlaps next compute) ----
        if (t + 1 < NT) {
#pragma unroll
            for (int p = 0; p < 4; p++) {
                *(float4*)&sm.kv.Kp[cur ^ 1][p*16 + lrK][acK] = pk[p];
                *(float4*)&sm.kv.Vp[cur ^ 1][p*8 + lrV][acV] = pv[p];
            }
        }
        __syncthreads();
    }

    // ---- finalize: quad-reduce l, O /= l, write [b][n][h*32+d] ----
    int b = bh >> 3, h = bh & 7;
    size_t base = (size_t)b * SEQ * 256 + h * HD;
#pragma unroll
    for (int mt = 0; mt < 2; mt++) {
        float l0 = l_i[mt][0], l1 = l_i[mt][1];
        l0 += __shfl_xor_sync(0xffffffffu, l0, 1);
        l0 += __shfl_xor_sync(0xffffffffu, l0, 2);
        l1 += __shfl_xor_sync(0xffffffffu, l1, 1);
        l1 += __shfl_xor_sync(0xffffffffu, l1, 2);
        float inv0 = 1.f / l0, inv1 = 1.f / l1;
        int rowa = q0 + warp*32 + mt*16 + g;
#pragma unroll
        for (int nt = 0; nt < 4; nt++) {
            int d = nt*8 + 2*tg;
            g_o[base + (size_t)rowa       * 256 + d    ] = o[mt][nt][0] * inv0;
            g_o[base + (size_t)rowa       * 256 + d + 1] = o[mt][nt][1] * inv0;
            g_o[base + (size_t)(rowa + 8) * 256 + d    ] = o[mt][nt][2] * inv1;
            g_o[base + (size_t)(rowa + 8) * 256 + d + 1] = o[mt][nt][3] * inv1;
        }
    }
}

// ---------------------------------------------------------------------------
extern "C" void kernel_launch(void* const* d_in, const int* in_sizes, int n_in,
                              void* d_out, int out_size)
{
    const float* x      = (const float*)d_in[0];
    const float* w_qkv  = (const float*)d_in[1];
    const float* b_qkv  = (const float*)d_in[2];
    const float* w_proj = (const float*)d_in[3];
    const float* b_proj = (const float*)d_in[4];
    // d_in[5] rel_bias: per-head scalar, softmax-invariant -> unused
    float* out = (float*)d_out;

    pack_w_kernel<<<(256*768 + 256*256 + 255) / 256, 256>>>(w_qkv, w_proj);
    gemm_kernel<0><<<dim3(12, 128), 128>>>(x, b_qkv, nullptr, 8192, 768, 256);
    attn_kernel<<<dim3(SEQ / 128, BATCH * NH), 128>>>();
    gemm_kernel<1><<<dim3(4, 128), 128>>>(nullptr, b_proj, out, 8192, 256, 256);
}

// round 12
// speedup vs baseline: 1.0218x; 1.0218x over previous
#include <cuda_runtime.h>
#include <cstdint>

#define SEQ 4096
#define HD 32
#define NH 8
#define BATCH 2

// Scratch (static device globals: allowed; no runtime allocation)
// g_q: [bh][n][d]          pre-scaled by 1/sqrt(32)*log2(e), tf32-rounded
// g_k: [bh][n][perm(d)]    pair-permuted for LDS.64 B-frags, tf32-rounded
// g_v: [bh][n/2][d][n&1]   row-pair interleaved, tf32-rounded
__device__ float g_q[BATCH*NH*SEQ*HD];
__device__ float g_k[BATCH*NH*SEQ*HD];
__device__ float g_v[BATCH*NH*SEQ*HD];
__device__ float g_o[BATCH*SEQ*NH*HD];   // [b][n][h*32+d]
// Pair-packed tf32 weights: Wp[((a*4+b)*N + c)*2 + i] = tf32(W[8a+b+4i][c])
__device__ float g_wqkv_p[256*768];
__device__ float g_wproj_p[256*256];

__device__ __forceinline__ float to_tf32(float x){
    uint32_t r; asm("cvt.rna.tf32.f32 %0, %1;" : "=r"(r) : "f"(x));
    return __uint_as_float(r);
}
__device__ __forceinline__ float ex2(float x){
    float y; asm("ex2.approx.f32 %0, %1;" : "=f"(y) : "f"(x)); return y;
}
__device__ __forceinline__ uint32_t fu(float x){ return __float_as_uint(x); }

__device__ __forceinline__ void mma8(float* c, const uint32_t* a, const uint32_t* b){
    asm volatile("mma.sync.aligned.m16n8k8.row.col.f32.tf32.tf32.f32 "
        "{%0,%1,%2,%3}, {%4,%5,%6,%7}, {%8,%9}, {%0,%1,%2,%3};\n"
        : "+f"(c[0]), "+f"(c[1]), "+f"(c[2]), "+f"(c[3])
        : "r"(a[0]), "r"(a[1]), "r"(a[2]), "r"(a[3]), "r"(b[0]), "r"(b[1]));
}
__device__ __forceinline__ float4 cvt4(float4 v){
    v.x = to_tf32(v.x); v.y = to_tf32(v.y); v.z = to_tf32(v.z); v.w = to_tf32(v.w);
    return v;
}

#define ATT_SCALE (0.17677669529663687f * 1.4426950408889634f)  // 1/sqrt(32)*log2(e)

// ---------------------------------------------------------------------------
// Weight pre-pack: Wp[a][b][c][i] = tf32(W[8a+b+4i][c])   (one-shot per call)
// ---------------------------------------------------------------------------
__global__ void pack_w_kernel(const float* __restrict__ Wq,
                              const float* __restrict__ Wj)
{
    int idx = blockIdx.x * blockDim.x + threadIdx.x;
    const int NQ = 256*768;
    if (idx < NQ) {
        int i = idx & 1;
        int c = (idx >> 1) % 768;
        int ab = (idx >> 1) / 768;
        int a = ab >> 2, b = ab & 3;
        g_wqkv_p[idx] = to_tf32(Wq[(size_t)(8*a + b + 4*i)*768 + c]);
    } else {
        int e = idx - NQ;
        if (e < 256*256) {
            int i = e & 1;
            int c = (e >> 1) % 256;
            int ab = (e >> 1) / 256;
            int a = ab >> 2, b = ab & 3;
            g_wproj_p[e] = to_tf32(Wj[(size_t)(8*a + b + 4*i)*256 + c]);
        }
    }
}

// ---------------------------------------------------------------------------
// tf32 GEMM with pair-packed B.  MODE 0: scatter packed q/k/v.  MODE 1: ->Out.
// BM=BN=64, BK=32, 128 threads (2x2 warps of 32x32).
// B path: global Wp -> smem = raw f4 copy (no cvt); B-frag = single LDS.64.
// Bsp row stride 136 floats: STS.128 phases and LDS.64 both conflict-free.
// ---------------------------------------------------------------------------
template<int MODE>
__global__ __launch_bounds__(128) void gemm_kernel(
    const float* __restrict__ Ain, const float* __restrict__ bias,
    float* __restrict__ Out, int M, int Nout, int K)
{
    __shared__ float As[64][36];
    __shared__ float Bsp[16][136];   // rows (a_off*4+b), 64 f2 pairs + pad

    const float* A  = (MODE == 1) ? (const float*)g_o : Ain;
    const float* Wp = (MODE == 1) ? g_wproj_p : g_wqkv_p;

    int tid = threadIdx.x;
    int warp = tid >> 5, lane = tid & 31;
    int wm = warp >> 1, wn = warp & 1;
    int g = lane >> 2, tg = lane & 3;
    int row0 = blockIdx.y * 64, col0 = blockIdx.x * 64;

    float acc[2][4][4];
#pragma unroll
    for (int i = 0; i < 2; i++)
#pragma unroll
        for (int j = 0; j < 4; j++)
#pragma unroll
            for (int r = 0; r < 4; r++) acc[i][j][r] = 0.f;

    int ar = tid >> 3, ac = (tid & 7) * 4;   // A loader
    int br = tid >> 3, bl = tid & 7;         // B loader: row br (=a_off*4+b), f4 lane bl

    float4 ra[4], rb[4];
#pragma unroll
    for (int i = 0; i < 4; i++) {
        ra[i] = *(const float4*)(A + (size_t)(row0 + ar + i*16) * K + ac);
        rb[i] = *(const float4*)(Wp
                + ((size_t)((0 + (br >> 2))*4 + (br & 3)) * Nout + col0) * 2
                + (bl + i*8) * 4);
    }

    for (int k0 = 0; k0 < K; k0 += 32) {
#pragma unroll
        for (int i = 0; i < 4; i++) {
            *(float4*)&As[ar + i*16][ac] = cvt4(ra[i]);
            *(float4*)&Bsp[br][(bl + i*8)*4] = rb[i];   // raw copy, pre-rounded
        }
        __syncthreads();

        if (k0 + 32 < K) {
            int a0 = (k0 + 32) >> 3;
#pragma unroll
            for (int i = 0; i < 4; i++) {
                ra[i] = *(const float4*)(A + (size_t)(row0 + ar + i*16) * K + k0 + 32 + ac);
                rb[i] = *(const float4*)(Wp
                        + ((size_t)((a0 + (br >> 2))*4 + (br & 3)) * Nout + col0) * 2
                        + (bl + i*8) * 4);
            }
        }

#pragma unroll
        for (int kk = 0; kk < 32; kk += 8) {
            int prow = (kk >> 3)*4 + tg;
            uint32_t af[2][4], bf[4][2];
#pragma unroll
            for (int mt = 0; mt < 2; mt++) {
                int r = wm*32 + mt*16;
                af[mt][0] = fu(As[r + g    ][kk + tg    ]);
                af[mt][1] = fu(As[r + g + 8][kk + tg    ]);
                af[mt][2] = fu(As[r + g    ][kk + tg + 4]);
                af[mt][3] = fu(As[r + g + 8][kk + tg + 4]);
            }
#pragma unroll
            for (int nt = 0; nt < 4; nt++) {
                float2 p = *(const float2*)&Bsp[prow][(wn*32 + nt*8 + g)*2];
                bf[nt][0] = fu(p.x);
                bf[nt][1] = fu(p.y);
            }
#pragma unroll
            for (int mt = 0; mt < 2; mt++)
#pragma unroll
                for (int nt = 0; nt < 4; nt++)
                    mma8(acc[mt][nt], af[mt], bf[nt]);
        }
        __syncthreads();
    }

#pragma unroll
    for (int mt = 0; mt < 2; mt++) {
#pragma unroll
        for (int nt = 0; nt < 4; nt++) {
#pragma unroll
            for (int rr = 0; rr < 4; rr++) {
                int r = row0 + wm*32 + mt*16 + g + ((rr >= 2) ? 8 : 0);
                int c = col0 + wn*32 + nt*8 + 2*tg + (rr & 1);
                float val = acc[mt][nt][rr] + bias[c];
                if (MODE == 0) {
                    int which = c >> 8, head = (c >> 5) & 7, d = c & 31;
                    int b = r >> 12, n = r & 4095;
                    int bh = b*8 + head;
                    if (which == 0) {
                        g_q[((size_t)bh*SEQ + n)*HD + d] = to_tf32(val * ATT_SCALE);
                    } else if (which == 1) {
                        int p = ((d >> 3) << 3) + 2*(d & 3) + ((d >> 2) & 1);
                        g_k[((size_t)bh*SEQ + n)*HD + p] = to_tf32(val);
                    } else {
                        g_v[(size_t)bh*SEQ*HD + (size_t)(n >> 1)*64 + 2*d + (n & 1)]
                            = to_tf32(val);
                    }
                } else {
                    Out[(size_t)r * 256 + c] = val;
                }
            }
        }
    }
}

// ---------------------------------------------------------------------------
// Flash attention v5 (occ 3 — R10-proven): BM=128, 128 thr = 4 warps x 32 rows.
// Pre-packed q/k/v from gemm<0>; double-buffered Kp/Vp; one barrier per tile;
// fixed-reference softmax; per-j QK->ex2->PV pipeline; raw-bits P.
// ---------------------------------------------------------------------------
__global__ __launch_bounds__(128, 3) void attn_kernel()
{
    __shared__ union SM {
        float Qs[128][36];                                  // phase 1 only
        struct { float Kp[2][64][40]; float Vp[2][32][72]; } kv;  // mainloop
    } sm;

    int tid = threadIdx.x, warp = tid >> 5, lane = tid & 31;
    int g = lane >> 2, tg = lane & 3;
    int bh = blockIdx.y;
    const float* qb = g_q + (size_t)bh * SEQ * HD;
    const float* kb = g_k + (size_t)bh * SEQ * HD;
    const float* vb = g_v + (size_t)bh * SEQ * HD;   // pair-interleaved rows of 64
    int q0 = blockIdx.x * 128;

    int lrK = tid >> 3, acK = (tid & 7) * 4;    // K loader: 16 rows/pass, f4 cols
    int lrV = tid >> 4, acV = (tid & 15) * 4;   // V loader: 8 pair-rows/pass

    // ---- phase 1: Q load (already scaled+rounded) + fragment hoist ----
#pragma unroll
    for (int p = 0; p < 8; p++) {
        int row = p*16 + lrK;
        *(float4*)&sm.Qs[row][acK] =
            *(const float4*)(qb + (size_t)(q0 + row) * HD + acK);
    }
    __syncthreads();

    uint32_t qf[2][4][4];
#pragma unroll
    for (int mt = 0; mt < 2; mt++) {
        int r = warp*32 + mt*16;
#pragma unroll
        for (int k4 = 0; k4 < 4; k4++) {
            int kk = k4 * 8;
            qf[mt][k4][0] = fu(sm.Qs[r + g    ][kk + tg    ]);
            qf[mt][k4][1] = fu(sm.Qs[r + g + 8][kk + tg    ]);
            qf[mt][k4][2] = fu(sm.Qs[r + g    ][kk + tg + 4]);
            qf[mt][k4][3] = fu(sm.Qs[r + g + 8][kk + tg + 4]);
        }
    }
    __syncthreads();   // all hoists done before union reused as Kp/Vp

    float l_i[2][2] = {{0.f, 0.f}, {0.f, 0.f}};
    float o[2][4][4];
#pragma unroll
    for (int mt = 0; mt < 2; mt++)
#pragma unroll
        for (int j = 0; j < 4; j++)
#pragma unroll
            for (int r = 0; r < 4; r++) o[mt][j][r] = 0.f;

    // ---- tile 0: load + publish into buffer 0 ----
    float4 pk[4], pv[4];
#pragma unroll
    for (int p = 0; p < 4; p++) {
        pk[p] = *(const float4*)(kb + (size_t)(p*16 + lrK) * HD + acK);
        pv[p] = *(const float4*)(vb + (size_t)(p*8 + lrV) * 64 + acV);
    }
#pragma unroll
    for (int p = 0; p < 4; p++) {
        *(float4*)&sm.kv.Kp[0][p*16 + lrK][acK] = pk[p];
        *(float4*)&sm.kv.Vp[0][p*8 + lrV][acV] = pv[p];
    }
    __syncthreads();

    const int NT = SEQ / 64;
    for (int t = 0; t < NT; t++) {
        int cur = t & 1;

        if (t + 1 < NT) {
            int kv = (t + 1) * 64;
#pragma unroll
            for (int p = 0; p < 4; p++) {
                pk[p] = *(const float4*)(kb + (size_t)(kv + p*16 + lrK) * HD + acK);
                pv[p] = *(const float4*)(vb + (size_t)((kv >> 1) + p*8 + lrV) * 64 + acV);
            }
        }

        // ---- per-j pipeline: QK(j) -> ex2(j) -> PV(j) on buffer cur ----
#pragma unroll
        for (int j = 0; j < 8; j++) {
            float s0[4] = {0.f,0.f,0.f,0.f};
            float s1[4] = {0.f,0.f,0.f,0.f};
#pragma unroll
            for (int k4 = 0; k4 < 4; k4++) {
                float2 kpair = *(const float2*)&sm.kv.Kp[cur][j*8 + g][(k4*4 + tg)*2];
                uint32_t bf[2] = { fu(kpair.x), fu(kpair.y) };
                mma8(s0, qf[0][k4], bf);
                mma8(s1, qf[1][k4], bf);
            }
#pragma unroll
            for (int r = 0; r < 4; r++) { s0[r] = ex2(s0[r]); s1[r] = ex2(s1[r]); }
            l_i[0][0] += s0[0] + s0[1];
            l_i[0][1] += s0[2] + s0[3];
            l_i[1][0] += s1[0] + s1[1];
            l_i[1][1] += s1[2] + s1[3];

            uint32_t af0[4] = { fu(s0[0]), fu(s0[2]), fu(s0[1]), fu(s0[3]) };
            uint32_t af1[4] = { fu(s1[0]), fu(s1[2]), fu(s1[1]), fu(s1[3]) };
#pragma unroll
            for (int ntd = 0; ntd < 4; ntd++) {
                float2 vpair = *(const float2*)&sm.kv.Vp[cur][4*j + tg][(ntd*8 + g)*2];
                uint32_t bf[2] = { fu(vpair.x), fu(vpair.y) };
                mma8(o[0][ntd], af0, bf);
                mma8(o[1][ntd], af1, bf);
            }
        }

        // ---- publish tile t+1 into the other buffer (overlaps next compute) ----
        if (t + 1 < NT) {
#pragma unroll
            for (int p = 0; p < 4; p++) {
                *(float4*)&sm.kv.Kp[cur ^ 1][p*16 + lrK][acK] = pk[p];
                *(float4*)&sm.kv.Vp[cur ^ 1][p*8 + lrV][acV] = pv[p];
            }
        }
        __syncthreads();
    }

    // ---- finalize: quad-reduce l, O /= l, write [b][n][h*32+d] ----
    int b = bh >> 3, h = bh & 7;
    size_t base = (size_t)b * SEQ * 256 + h * HD;
#pragma unroll
    for (int mt = 0; mt < 2; mt++) {
        float l0 = l_i[mt][0], l1 = l_i[mt][1];
        l0 += __shfl_xor_sync(0xffffffffu, l0, 1);
        l0 += __shfl_xor_sync(0xffffffffu, l0, 2);
        l1 += __shfl_xor_sync(0xffffffffu, l1, 1);
        l1 += __shfl_xor_sync(0xffffffffu, l1, 2);
        float inv0 = 1.f / l0, inv1 = 1.f / l1;
        int rowa = q0 + warp*32 + mt*16 + g;
#pragma unroll
        for (int nt = 0; nt < 4; nt++) {
            int d = nt*8 + 2*tg;
            g_o[base + (size_t)rowa       * 256 + d    ] = o[mt][nt][0] * inv0;
            g_o[base + (size_t)rowa       * 256 + d + 1] = o[mt][nt][1] * inv0;
            g_o[base + (size_t)(rowa + 8) * 256 + d    ] = o[mt][nt][2] * inv1;
            g_o[base + (size_t)(rowa + 8) * 256 + d + 1] = o[mt][nt][3] * inv1;
        }
    }
}

// ---------------------------------------------------------------------------
extern "C" void kernel_launch(void* const* d_in, const int* in_sizes, int n_in,
                              void* d_out, int out_size)
{
    const float* x      = (const float*)d_in[0];
    const float* w_qkv  = (const float*)d_in[1];
    const float* b_qkv  = (const float*)d_in[2];
    const float* w_proj = (const float*)d_in[3];
    const float* b_proj = (const float*)d_in[4];
    // d_in[5] rel_bias: per-head scalar, softmax-invariant -> unused
    float* out = (float*)d_out;

    pack_w_kernel<<<(256*768 + 256*256 + 255) / 256, 256>>>(w_qkv, w_proj);
    gemm_kernel<0><<<dim3(12, 128), 128>>>(x, b_qkv, nullptr, 8192, 768, 256);
    attn_kernel<<<dim3(SEQ / 128, BATCH * NH), 128>>>();
    gemm_kernel<1><<<dim3(4, 128), 128>>>(nullptr, b_proj, out, 8192, 256, 256);
}

// round 13
// speedup vs baseline: 1.1028x; 1.0793x over previous
#include <cuda_runtime.h>
#include <cstdint>

#define SEQ 4096
#define HD 32
#define NH 8
#define BATCH 2

// Scratch (static device globals: allowed; no runtime allocation)
// g_q: [bh][n][d]          pre-scaled by 1/sqrt(32)*log2(e), tf32-rounded
// g_k: [bh][n][perm(d)]    pair-permuted for LDS.64 B-frags, tf32-rounded
// g_v: [bh][n/2][d][n&1]   row-pair interleaved, tf32-rounded
__device__ float g_q[BATCH*NH*SEQ*HD];
__device__ float g_k[BATCH*NH*SEQ*HD];
__device__ float g_v[BATCH*NH*SEQ*HD];
__device__ float g_o[BATCH*SEQ*NH*HD];   // [b][n][h*32+d]
// Pair-packed tf32 weights: Wp[((a*4+b)*N + c)*2 + i] = tf32(W[8a+b+4i][c])
__device__ float g_wqkv_p[256*768];
__device__ float g_wproj_p[256*256];

__device__ __forceinline__ float to_tf32(float x){
    uint32_t r; asm("cvt.rna.tf32.f32 %0, %1;" : "=r"(r) : "f"(x));
    return __uint_as_float(r);
}
__device__ __forceinline__ float ex2(float x){
    float y; asm("ex2.approx.f32 %0, %1;" : "=f"(y) : "f"(x)); return y;
}
__device__ __forceinline__ uint32_t fu(float x){ return __float_as_uint(x); }

__device__ __forceinline__ void mma8(float* c, const uint32_t* a, const uint32_t* b){
    asm volatile("mma.sync.aligned.m16n8k8.row.col.f32.tf32.tf32.f32 "
        "{%0,%1,%2,%3}, {%4,%5,%6,%7}, {%8,%9}, {%0,%1,%2,%3};\n"
        : "+f"(c[0]), "+f"(c[1]), "+f"(c[2]), "+f"(c[3])
        : "r"(a[0]), "r"(a[1]), "r"(a[2]), "r"(a[3]), "r"(b[0]), "r"(b[1]));
}
__device__ __forceinline__ float4 cvt4(float4 v){
    v.x = to_tf32(v.x); v.y = to_tf32(v.y); v.z = to_tf32(v.z); v.w = to_tf32(v.w);
    return v;
}
// 16-byte async copy global->shared (no registers, no cvt — data pre-rounded)
__device__ __forceinline__ void cp16(uint32_t saddr, const void* gptr){
    asm volatile("cp.async.cg.shared.global [%0], [%1], 16;"
                 :: "r"(saddr), "l"(gptr) : "memory");
}
__device__ __forceinline__ void cp_commit(){
    asm volatile("cp.async.commit_group;" ::: "memory");
}
__device__ __forceinline__ void cp_wait0(){
    asm volatile("cp.async.wait_group 0;" ::: "memory");
}

#define ATT_SCALE (0.17677669529663687f * 1.4426950408889634f)  // 1/sqrt(32)*log2(e)

// ---------------------------------------------------------------------------
// Weight pre-pack: Wp[a][b][c][i] = tf32(W[8a+b+4i][c])   (one-shot per call)
// ---------------------------------------------------------------------------
__global__ void pack_w_kernel(const float* __restrict__ Wq,
                              const float* __restrict__ Wj)
{
    int idx = blockIdx.x * blockDim.x + threadIdx.x;
    const int NQ = 256*768;
    if (idx < NQ) {
        int i = idx & 1;
        int c = (idx >> 1) % 768;
        int ab = (idx >> 1) / 768;
        int a = ab >> 2, b = ab & 3;
        g_wqkv_p[idx] = to_tf32(Wq[(size_t)(8*a + b + 4*i)*768 + c]);
    } else {
        int e = idx - NQ;
        if (e < 256*256) {
            int i = e & 1;
            int c = (e >> 1) % 256;
            int ab = (e >> 1) / 256;
            int a = ab >> 2, b = ab & 3;
            g_wproj_p[e] = to_tf32(Wj[(size_t)(8*a + b + 4*i)*256 + c]);
        }
    }
}

// ---------------------------------------------------------------------------
// tf32 GEMM with pair-packed B.  MODE 0: scatter packed q/k/v.  MODE 1: ->Out.
// BM=BN=64, BK=32, 128 threads (2x2 warps of 32x32).   [unchanged from R12]
// ---------------------------------------------------------------------------
template<int MODE>
__global__ __launch_bounds__(128) void gemm_kernel(
    const float* __restrict__ Ain, const float* __restrict__ bias,
    float* __restrict__ Out, int M, int Nout, int K)
{
    __shared__ float As[64][36];
    __shared__ float Bsp[16][136];   // rows (a_off*4+b), 64 f2 pairs + pad

    const float* A  = (MODE == 1) ? (const float*)g_o : Ain;
    const float* Wp = (MODE == 1) ? g_wproj_p : g_wqkv_p;

    int tid = threadIdx.x;
    int warp = tid >> 5, lane = tid & 31;
    int wm = warp >> 1, wn = warp & 1;
    int g = lane >> 2, tg = lane & 3;
    int row0 = blockIdx.y * 64, col0 = blockIdx.x * 64;

    float acc[2][4][4];
#pragma unroll
    for (int i = 0; i < 2; i++)
#pragma unroll
        for (int j = 0; j < 4; j++)
#pragma unroll
            for (int r = 0; r < 4; r++) acc[i][j][r] = 0.f;

    int ar = tid >> 3, ac = (tid & 7) * 4;   // A loader
    int br = tid >> 3, bl = tid & 7;         // B loader

    float4 ra[4], rb[4];
#pragma unroll
    for (int i = 0; i < 4; i++) {
        ra[i] = *(const float4*)(A + (size_t)(row0 + ar + i*16) * K + ac);
        rb[i] = *(const float4*)(Wp
                + ((size_t)((0 + (br >> 2))*4 + (br & 3)) * Nout + col0) * 2
                + (bl + i*8) * 4);
    }

    for (int k0 = 0; k0 < K; k0 += 32) {
#pragma unroll
        for (int i = 0; i < 4; i++) {
            *(float4*)&As[ar + i*16][ac] = cvt4(ra[i]);
            *(float4*)&Bsp[br][(bl + i*8)*4] = rb[i];   // raw copy, pre-rounded
        }
        __syncthreads();

        if (k0 + 32 < K) {
            int a0 = (k0 + 32) >> 3;
#pragma unroll
            for (int i = 0; i < 4; i++) {
                ra[i] = *(const float4*)(A + (size_t)(row0 + ar + i*16) * K + k0 + 32 + ac);
                rb[i] = *(const float4*)(Wp
                        + ((size_t)((a0 + (br >> 2))*4 + (br & 3)) * Nout + col0) * 2
                        + (bl + i*8) * 4);
            }
        }

#pragma unroll
        for (int kk = 0; kk < 32; kk += 8) {
            int prow = (kk >> 3)*4 + tg;
            uint32_t af[2][4], bf[4][2];
#pragma unroll
            for (int mt = 0; mt < 2; mt++) {
                int r = wm*32 + mt*16;
                af[mt][0] = fu(As[r + g    ][kk + tg    ]);
                af[mt][1] = fu(As[r + g + 8][kk + tg    ]);
                af[mt][2] = fu(As[r + g    ][kk + tg + 4]);
                af[mt][3] = fu(As[r + g + 8][kk + tg + 4]);
            }
#pragma unroll
            for (int nt = 0; nt < 4; nt++) {
                float2 p = *(const float2*)&Bsp[prow][(wn*32 + nt*8 + g)*2];
                bf[nt][0] = fu(p.x);
                bf[nt][1] = fu(p.y);
            }
#pragma unroll
            for (int mt = 0; mt < 2; mt++)
#pragma unroll
                for (int nt = 0; nt < 4; nt++)
                    mma8(acc[mt][nt], af[mt], bf[nt]);
        }
        __syncthreads();
    }

#pragma unroll
    for (int mt = 0; mt < 2; mt++) {
#pragma unroll
        for (int nt = 0; nt < 4; nt++) {
#pragma unroll
            for (int rr = 0; rr < 4; rr++) {
                int r = row0 + wm*32 + mt*16 + g + ((rr >= 2) ? 8 : 0);
                int c = col0 + wn*32 + nt*8 + 2*tg + (rr & 1);
                float val = acc[mt][nt][rr] + bias[c];
                if (MODE == 0) {
                    int which = c >> 8, head = (c >> 5) & 7, d = c & 31;
                    int b = r >> 12, n = r & 4095;
                    int bh = b*8 + head;
                    if (which == 0) {
                        g_q[((size_t)bh*SEQ + n)*HD + d] = to_tf32(val * ATT_SCALE);
                    } else if (which == 1) {
                        int p = ((d >> 3) << 3) + 2*(d & 3) + ((d >> 2) & 1);
                        g_k[((size_t)bh*SEQ + n)*HD + p] = to_tf32(val);
                    } else {
                        g_v[(size_t)bh*SEQ*HD + (size_t)(n >> 1)*64 + 2*d + (n & 1)]
                            = to_tf32(val);
                    }
                } else {
                    Out[(size_t)r * 256 + c] = val;
                }
            }
        }
    }
}

// ---------------------------------------------------------------------------
// Flash attention v6: BM=128, 128 thr, occ 4 (single wave: 512 CTAs <= 592).
// K/V staged via cp.async (zero register footprint, async latency hiding);
// double-buffered smem; fixed-reference softmax; per-j QK->ex2->PV pipeline.
// ---------------------------------------------------------------------------
__global__ __launch_bounds__(128, 4) void attn_kernel()
{
    __shared__ __align__(16) union SM {
        float Qs[128][36];                                  // phase 1 only
        struct { float Kp[2][64][40]; float Vp[2][32][72]; } kv;  // mainloop
    } sm;

    int tid = threadIdx.x, warp = tid >> 5, lane = tid & 31;
    int g = lane >> 2, tg = lane & 3;
    int bh = blockIdx.y;
    const float* qb = g_q + (size_t)bh * SEQ * HD;
    const float* kb = g_k + (size_t)bh * SEQ * HD;
    const float* vb = g_v + (size_t)bh * SEQ * HD;   // pair-interleaved rows of 64
    int q0 = blockIdx.x * 128;

    int lrK = tid >> 3, acK = (tid & 7) * 4;    // K loader: 16 rows/pass, f4 cols
    int lrV = tid >> 4, acV = (tid & 15) * 4;   // V loader: 8 pair-rows/pass

    // ---- phase 1: Q load (already scaled+rounded) + fragment hoist ----
#pragma unroll
    for (int p = 0; p < 8; p++) {
        int row = p*16 + lrK;
        *(float4*)&sm.Qs[row][acK] =
            *(const float4*)(qb + (size_t)(q0 + row) * HD + acK);
    }
    __syncthreads();

    uint32_t qf[2][4][4];
#pragma unroll
    for (int mt = 0; mt < 2; mt++) {
        int r = warp*32 + mt*16;
#pragma unroll
        for (int k4 = 0; k4 < 4; k4++) {
            int kk = k4 * 8;
            qf[mt][k4][0] = fu(sm.Qs[r + g    ][kk + tg    ]);
            qf[mt][k4][1] = fu(sm.Qs[r + g + 8][kk + tg    ]);
            qf[mt][k4][2] = fu(sm.Qs[r + g    ][kk + tg + 4]);
            qf[mt][k4][3] = fu(sm.Qs[r + g + 8][kk + tg + 4]);
        }
    }
    __syncthreads();   // all hoists done before union reused as Kp/Vp

    // smem byte addresses for this thread's staging slots
    uint32_t kS[2], vS[2];
#pragma unroll
    for (int bufi = 0; bufi < 2; bufi++) {
        kS[bufi] = (uint32_t)__cvta_generic_to_shared(&sm.kv.Kp[bufi][lrK][acK]);
        vS[bufi] = (uint32_t)__cvta_generic_to_shared(&sm.kv.Vp[bufi][lrV][acV]);
    }
    const uint32_t KROW = 40*4, VROW = 72*4;   // row strides in bytes

    float l_i[2][2] = {{0.f, 0.f}, {0.f, 0.f}};
    float o[2][4][4];
#pragma unroll
    for (int mt = 0; mt < 2; mt++)
#pragma unroll
        for (int j = 0; j < 4; j++)
#pragma unroll
            for (int r = 0; r < 4; r++) o[mt][j][r] = 0.f;

    // ---- tile 0 -> buffer 0 via cp.async ----
#pragma unroll
    for (int p = 0; p < 4; p++) {
        cp16(kS[0] + p*16*KROW, kb + (size_t)(p*16 + lrK) * HD + acK);
        cp16(vS[0] + p*8*VROW,  vb + (size_t)(p*8 + lrV) * 64 + acV);
    }
    cp_commit();
    cp_wait0();
    __syncthreads();

    const int NT = SEQ / 64;
    for (int t = 0; t < NT; t++) {
        int cur = t & 1;

        // ---- stage tile t+1 into the other buffer (async, overlaps compute) ----
        if (t + 1 < NT) {
            int kv = (t + 1) * 64;
#pragma unroll
            for (int p = 0; p < 4; p++) {
                cp16(kS[cur ^ 1] + p*16*KROW, kb + (size_t)(kv + p*16 + lrK) * HD + acK);
                cp16(vS[cur ^ 1] + p*8*VROW,  vb + (size_t)((kv >> 1) + p*8 + lrV) * 64 + acV);
            }
            cp_commit();
        }

        // ---- per-j pipeline: QK(j) -> ex2(j) -> PV(j) on buffer cur ----
#pragma unroll
        for (int j = 0; j < 8; j++) {
            float s0[4] = {0.f,0.f,0.f,0.f};
            float s1[4] = {0.f,0.f,0.f,0.f};
#pragma unroll
            for (int k4 = 0; k4 < 4; k4++) {
                float2 kpair = *(const float2*)&sm.kv.Kp[cur][j*8 + g][(k4*4 + tg)*2];
                uint32_t bf[2] = { fu(kpair.x), fu(kpair.y) };
                mma8(s0, qf[0][k4], bf);
                mma8(s1, qf[1][k4], bf);
            }
#pragma unroll
            for (int r = 0; r < 4; r++) { s0[r] = ex2(s0[r]); s1[r] = ex2(s1[r]); }
            l_i[0][0] += s0[0] + s0[1];
            l_i[0][1] += s0[2] + s0[3];
            l_i[1][0] += s1[0] + s1[1];
            l_i[1][1] += s1[2] + s1[3];

            uint32_t af0[4] = { fu(s0[0]), fu(s0[2]), fu(s0[1]), fu(s0[3]) };
            uint32_t af1[4] = { fu(s1[0]), fu(s1[2]), fu(s1[1]), fu(s1[3]) };
#pragma unroll
            for (int ntd = 0; ntd < 4; ntd++) {
                float2 vpair = *(const float2*)&sm.kv.Vp[cur][4*j + tg][(ntd*8 + g)*2];
                uint32_t bf[2] = { fu(vpair.x), fu(vpair.y) };
                mma8(o[0][ntd], af0, bf);
                mma8(o[1][ntd], af1, bf);
            }
        }

        // ---- tile t+1 staged + everyone done reading buffer cur ----
        cp_wait0();
        __syncthreads();
    }

    // ---- finalize: quad-reduce l, O /= l, write [b][n][h*32+d] ----
    int b = bh >> 3, h = bh & 7;
    size_t base = (size_t)b * SEQ * 256 + h * HD;
#pragma unroll
    for (int mt = 0; mt < 2; mt++) {
        float l0 = l_i[mt][0], l1 = l_i[mt][1];
        l0 += __shfl_xor_sync(0xffffffffu, l0, 1);
        l0 += __shfl_xor_sync(0xffffffffu, l0, 2);
        l1 += __shfl_xor_sync(0xffffffffu, l1, 1);
        l1 += __shfl_xor_sync(0xffffffffu, l1, 2);
        float inv0 = 1.f / l0, inv1 = 1.f / l1;
        int rowa = q0 + warp*32 + mt*16 + g;
#pragma unroll
        for (int nt = 0; nt < 4; nt++) {
            int d = nt*8 + 2*tg;
            g_o[base + (size_t)rowa       * 256 + d    ] = o[mt][nt][0] * inv0;
            g_o[base + (size_t)rowa       * 256 + d + 1] = o[mt][nt][1] * inv0;
            g_o[base + (size_t)(rowa + 8) * 256 + d    ] = o[mt][nt][2] * inv1;
            g_o[base + (size_t)(rowa + 8) * 256 + d + 1] = o[mt][nt][3] * inv1;
        }
    }
}

// ---------------------------------------------------------------------------
extern "C" void kernel_launch(void* const* d_in, const int* in_sizes, int n_in,
                              void* d_out, int out_size)
{
    const float* x      = (const float*)d_in[0];
    const float* w_qkv  = (const float*)d_in[1];
    const float* b_qkv  = (const float*)d_in[2];
    const float* w_proj = (const float*)d_in[3];
    const float* b_proj = (const float*)d_in[4];
    // d_in[5] rel_bias: per-head scalar, softmax-invariant -> unused
    float* out = (float*)d_out;

    pack_w_kernel<<<(256*768 + 256*256 + 255) / 256, 256>>>(w_qkv, w_proj);
    gemm_kernel<0><<<dim3(12, 128), 128>>>(x, b_qkv, nullptr, 8192, 768, 256);
    attn_kernel<<<dim3(SEQ / 128, BATCH * NH), 128>>>();
    gemm_kernel<1><<<dim3(4, 128), 128>>>(nullptr, b_proj, out, 8192, 256, 256);
}

// round 14
// speedup vs baseline: 1.1141x; 1.0103x over previous
#include <cuda_runtime.h>
#include <cstdint>

#define SEQ 4096
#define HD 32
#define NH 8
#define BATCH 2

// Scratch (static device globals: allowed; no runtime allocation)
// g_x: tf32-pre-rounded copy of input x
// g_q: [bh][n][d]          pre-scaled by 1/sqrt(32)*log2(e), tf32-rounded
// g_k: [bh][n][perm(d)]    pair-permuted for LDS.64 B-frags, tf32-rounded
// g_v: [bh][n/2][d][n&1]   row-pair interleaved, tf32-rounded
// g_o: [b][n][h*32+d]      tf32-rounded attention output
__device__ float g_x[BATCH*SEQ*256];
__device__ float g_q[BATCH*NH*SEQ*HD];
__device__ float g_k[BATCH*NH*SEQ*HD];
__device__ float g_v[BATCH*NH*SEQ*HD];
__device__ float g_o[BATCH*SEQ*NH*HD];
// Pair-packed tf32 weights: Wp[((a*4+b)*N + c)*2 + i] = tf32(W[8a+b+4i][c])
__device__ float g_wqkv_p[256*768];
__device__ float g_wproj_p[256*256];

__device__ __forceinline__ float to_tf32(float x){
    uint32_t r; asm("cvt.rna.tf32.f32 %0, %1;" : "=r"(r) : "f"(x));
    return __uint_as_float(r);
}
__device__ __forceinline__ float ex2(float x){
    float y; asm("ex2.approx.f32 %0, %1;" : "=f"(y) : "f"(x)); return y;
}
__device__ __forceinline__ uint32_t fu(float x){ return __float_as_uint(x); }

__device__ __forceinline__ void mma8(float* c, const uint32_t* a, const uint32_t* b){
    asm volatile("mma.sync.aligned.m16n8k8.row.col.f32.tf32.tf32.f32 "
        "{%0,%1,%2,%3}, {%4,%5,%6,%7}, {%8,%9}, {%0,%1,%2,%3};\n"
        : "+f"(c[0]), "+f"(c[1]), "+f"(c[2]), "+f"(c[3])
        : "r"(a[0]), "r"(a[1]), "r"(a[2]), "r"(a[3]), "r"(b[0]), "r"(b[1]));
}
// 16-byte async copy global->shared
__device__ __forceinline__ void cp16(uint32_t saddr, const void* gptr){
    asm volatile("cp.async.cg.shared.global [%0], [%1], 16;"
                 :: "r"(saddr), "l"(gptr) : "memory");
}
__device__ __forceinline__ void cp_commit(){
    asm volatile("cp.async.commit_group;" ::: "memory");
}
__device__ __forceinline__ void cp_wait0(){
    asm volatile("cp.async.wait_group 0;" ::: "memory");
}

#define ATT_SCALE (0.17677669529663687f * 1.4426950408889634f)  // 1/sqrt(32)*log2(e)

// ---------------------------------------------------------------------------
// One-shot pre-rounding kernels
// ---------------------------------------------------------------------------
__global__ void pack_x_kernel(const float* __restrict__ X)
{
    int i = (blockIdx.x * blockDim.x + threadIdx.x) * 4;
    float4 v = *(const float4*)(X + i);
    v.x = to_tf32(v.x); v.y = to_tf32(v.y); v.z = to_tf32(v.z); v.w = to_tf32(v.w);
    *(float4*)(g_x + i) = v;
}

__global__ void pack_w_kernel(const float* __restrict__ Wq,
                              const float* __restrict__ Wj)
{
    int idx = blockIdx.x * blockDim.x + threadIdx.x;
    const int NQ = 256*768;
    if (idx < NQ) {
        int i = idx & 1;
        int c = (idx >> 1) % 768;
        int ab = (idx >> 1) / 768;
        int a = ab >> 2, b = ab & 3;
        g_wqkv_p[idx] = to_tf32(Wq[(size_t)(8*a + b + 4*i)*768 + c]);
    } else {
        int e = idx - NQ;
        if (e < 256*256) {
            int i = e & 1;
            int c = (e >> 1) % 256;
            int ab = (e >> 1) / 256;
            int a = ab >> 2, b = ab & 3;
            g_wproj_p[e] = to_tf32(Wj[(size_t)(8*a + b + 4*i)*256 + c]);
        }
    }
}

// ---------------------------------------------------------------------------
// tf32 GEMM v2: fully cp.async, double-buffered, zero in-loop cvt.
// MODE 0: A=g_x, scatter packed q/k/v.  MODE 1: A=g_o, write Out.
// BM=BN=64, BK=32, 128 threads (2x2 warps of 32x32), ONE barrier per k0 iter.
// ---------------------------------------------------------------------------
template<int MODE>
__global__ __launch_bounds__(128) void gemm_kernel(
    const float* __restrict__ bias, float* __restrict__ Out,
    int M, int Nout, int K)
{
    __shared__ __align__(16) float As[2][64][36];
    __shared__ __align__(16) float Bsp[2][16][136];

    const float* A  = (MODE == 1) ? g_o : g_x;
    const float* Wp = (MODE == 1) ? g_wproj_p : g_wqkv_p;

    int tid = threadIdx.x;
    int warp = tid >> 5, lane = tid & 31;
    int wm = warp >> 1, wn = warp & 1;
    int g = lane >> 2, tg = lane & 3;
    int row0 = blockIdx.y * 64, col0 = blockIdx.x * 64;

    float acc[2][4][4];
#pragma unroll
    for (int i = 0; i < 2; i++)
#pragma unroll
        for (int j = 0; j < 4; j++)
#pragma unroll
            for (int r = 0; r < 4; r++) acc[i][j][r] = 0.f;

    int ar = tid >> 3, ac = (tid & 7) * 4;   // A loader: rows ar+16i
    int br = tid >> 3, bl = tid & 7;         // B loader: row br, f4 lane bl

    uint32_t aS[2], bS[2];
#pragma unroll
    for (int bufi = 0; bufi < 2; bufi++) {
        aS[bufi] = (uint32_t)__cvta_generic_to_shared(&As[bufi][ar][ac]);
        bS[bufi] = (uint32_t)__cvta_generic_to_shared(&Bsp[bufi][br][bl*4]);
    }
    const uint32_t AROW = 36*4;

    // stage k0=0 into buffer 0
#pragma unroll
    for (int i = 0; i < 4; i++) {
        cp16(aS[0] + i*16*AROW, A + (size_t)(row0 + ar + i*16) * K + ac);
        cp16(bS[0] + i*8*16,
             Wp + ((size_t)((0 + (br >> 2))*4 + (br & 3)) * Nout + col0) * 2 + (bl + i*8)*4);
    }
    cp_commit();
    cp_wait0();
    __syncthreads();

    for (int k0 = 0; k0 < K; k0 += 32) {
        int cur = (k0 >> 5) & 1;

        if (k0 + 32 < K) {
            int a0 = (k0 + 32) >> 3;
#pragma unroll
            for (int i = 0; i < 4; i++) {
                cp16(aS[cur ^ 1] + i*16*AROW,
                     A + (size_t)(row0 + ar + i*16) * K + k0 + 32 + ac);
                cp16(bS[cur ^ 1] + i*8*16,
                     Wp + ((size_t)((a0 + (br >> 2))*4 + (br & 3)) * Nout + col0) * 2
                        + (bl + i*8)*4);
            }
            cp_commit();
        }

#pragma unroll
        for (int kk = 0; kk < 32; kk += 8) {
            int prow = (kk >> 3)*4 + tg;
            uint32_t af[2][4], bf[4][2];
#pragma unroll
            for (int mt = 0; mt < 2; mt++) {
                int r = wm*32 + mt*16;
                af[mt][0] = fu(As[cur][r + g    ][kk + tg    ]);
                af[mt][1] = fu(As[cur][r + g + 8][kk + tg    ]);
                af[mt][2] = fu(As[cur][r + g    ][kk + tg + 4]);
                af[mt][3] = fu(As[cur][r + g + 8][kk + tg + 4]);
            }
#pragma unroll
            for (int nt = 0; nt < 4; nt++) {
                float2 p = *(const float2*)&Bsp[cur][prow][(wn*32 + nt*8 + g)*2];
                bf[nt][0] = fu(p.x);
                bf[nt][1] = fu(p.y);
            }
#pragma unroll
            for (int mt = 0; mt < 2; mt++)
#pragma unroll
                for (int nt = 0; nt < 4; nt++)
                    mma8(acc[mt][nt], af[mt], bf[nt]);
        }

        cp_wait0();
        __syncthreads();
    }

#pragma unroll
    for (int mt = 0; mt < 2; mt++) {
#pragma unroll
        for (int nt = 0; nt < 4; nt++) {
#pragma unroll
            for (int rr = 0; rr < 4; rr++) {
                int r = row0 + wm*32 + mt*16 + g + ((rr >= 2) ? 8 : 0);
                int c = col0 + wn*32 + nt*8 + 2*tg + (rr & 1);
                float val = acc[mt][nt][rr] + bias[c];
                if (MODE == 0) {
                    int which = c >> 8, head = (c >> 5) & 7, d = c & 31;
                    int b = r >> 12, n = r & 4095;
                    int bh = b*8 + head;
                    if (which == 0) {
                        g_q[((size_t)bh*SEQ + n)*HD + d] = to_tf32(val * ATT_SCALE);
                    } else if (which == 1) {
                        int p = ((d >> 3) << 3) + 2*(d & 3) + ((d >> 2) & 1);
                        g_k[((size_t)bh*SEQ + n)*HD + p] = to_tf32(val);
                    } else {
                        g_v[(size_t)bh*SEQ*HD + (size_t)(n >> 1)*64 + 2*d + (n & 1)]
                            = to_tf32(val);
                    }
                } else {
                    Out[(size_t)r * 256 + c] = val;
                }
            }
        }
    }
}

// ---------------------------------------------------------------------------
// Flash attention v6 (R13-proven): BM=128, 128 thr, occ 4, cp.async staging,
// double-buffered smem, fixed-reference softmax, per-j QK->ex2->PV pipeline.
// Finalize now stores tf32-rounded g_o (feeds gemm<1> raw).
// ---------------------------------------------------------------------------
__global__ __launch_bounds__(128, 4) void attn_kernel()
{
    __shared__ __align__(16) union SM {
        float Qs[128][36];                                  // phase 1 only
        struct { float Kp[2][64][40]; float Vp[2][32][72]; } kv;  // mainloop
    } sm;

    int tid = threadIdx.x, warp = tid >> 5, lane = tid & 31;
    int g = lane >> 2, tg = lane & 3;
    int bh = blockIdx.y;
    const float* qb = g_q + (size_t)bh * SEQ * HD;
    const float* kb = g_k + (size_t)bh * SEQ * HD;
    const float* vb = g_v + (size_t)bh * SEQ * HD;   // pair-interleaved rows of 64
    int q0 = blockIdx.x * 128;

    int lrK = tid >> 3, acK = (tid & 7) * 4;    // K loader: 16 rows/pass, f4 cols
    int lrV = tid >> 4, acV = (tid & 15) * 4;   // V loader: 8 pair-rows/pass

    // ---- phase 1: Q load (already scaled+rounded) + fragment hoist ----
#pragma unroll
    for (int p = 0; p < 8; p++) {
        int row = p*16 + lrK;
        *(float4*)&sm.Qs[row][acK] =
            *(const float4*)(qb + (size_t)(q0 + row) * HD + acK);
    }
    __syncthreads();

    uint32_t qf[2][4][4];
#pragma unroll
    for (int mt = 0; mt < 2; mt++) {
        int r = warp*32 + mt*16;
#pragma unroll
        for (int k4 = 0; k4 < 4; k4++) {
            int kk = k4 * 8;
            qf[mt][k4][0] = fu(sm.Qs[r + g    ][kk + tg    ]);
            qf[mt][k4][1] = fu(sm.Qs[r + g + 8][kk + tg    ]);
            qf[mt][k4][2] = fu(sm.Qs[r + g    ][kk + tg + 4]);
            qf[mt][k4][3] = fu(sm.Qs[r + g + 8][kk + tg + 4]);
        }
    }
    __syncthreads();   // all hoists done before union reused as Kp/Vp

    uint32_t kS[2], vS[2];
#pragma unroll
    for (int bufi = 0; bufi < 2; bufi++) {
        kS[bufi] = (uint32_t)__cvta_generic_to_shared(&sm.kv.Kp[bufi][lrK][acK]);
        vS[bufi] = (uint32_t)__cvta_generic_to_shared(&sm.kv.Vp[bufi][lrV][acV]);
    }
    const uint32_t KROW = 40*4, VROW = 72*4;

    float l_i[2][2] = {{0.f, 0.f}, {0.f, 0.f}};
    float o[2][4][4];
#pragma unroll
    for (int mt = 0; mt < 2; mt++)
#pragma unroll
        for (int j = 0; j < 4; j++)
#pragma unroll
            for (int r = 0; r < 4; r++) o[mt][j][r] = 0.f;

    // ---- tile 0 -> buffer 0 via cp.async ----
#pragma unroll
    for (int p = 0; p < 4; p++) {
        cp16(kS[0] + p*16*KROW, kb + (size_t)(p*16 + lrK) * HD + acK);
        cp16(vS[0] + p*8*VROW,  vb + (size_t)(p*8 + lrV) * 64 + acV);
    }
    cp_commit();
    cp_wait0();
    __syncthreads();

    const int NT = SEQ / 64;
    for (int t = 0; t < NT; t++) {
        int cur = t & 1;

        if (t + 1 < NT) {
            int kv = (t + 1) * 64;
#pragma unroll
            for (int p = 0; p < 4; p++) {
                cp16(kS[cur ^ 1] + p*16*KROW, kb + (size_t)(kv + p*16 + lrK) * HD + acK);
                cp16(vS[cur ^ 1] + p*8*VROW,  vb + (size_t)((kv >> 1) + p*8 + lrV) * 64 + acV);
            }
            cp_commit();
        }

        // ---- per-j pipeline: QK(j) -> ex2(j) -> PV(j) on buffer cur ----
#pragma unroll
        for (int j = 0; j < 8; j++) {
            float s0[4] = {0.f,0.f,0.f,0.f};
            float s1[4] = {0.f,0.f,0.f,0.f};
#pragma unroll
            for (int k4 = 0; k4 < 4; k4++) {
                float2 kpair = *(const float2*)&sm.kv.Kp[cur][j*8 + g][(k4*4 + tg)*2];
                uint32_t bf[2] = { fu(kpair.x), fu(kpair.y) };
                mma8(s0, qf[0][k4], bf);
                mma8(s1, qf[1][k4], bf);
            }
#pragma unroll
            for (int r = 0; r < 4; r++) { s0[r] = ex2(s0[r]); s1[r] = ex2(s1[r]); }
            l_i[0][0] += s0[0] + s0[1];
            l_i[0][1] += s0[2] + s0[3];
            l_i[1][0] += s1[0] + s1[1];
            l_i[1][1] += s1[2] + s1[3];

            uint32_t af0[4] = { fu(s0[0]), fu(s0[2]), fu(s0[1]), fu(s0[3]) };
            uint32_t af1[4] = { fu(s1[0]), fu(s1[2]), fu(s1[1]), fu(s1[3]) };
#pragma unroll
            for (int ntd = 0; ntd < 4; ntd++) {
                float2 vpair = *(const float2*)&sm.kv.Vp[cur][4*j + tg][(ntd*8 + g)*2];
                uint32_t bf[2] = { fu(vpair.x), fu(vpair.y) };
                mma8(o[0][ntd], af0, bf);
                mma8(o[1][ntd], af1, bf);
            }
        }

        cp_wait0();
        __syncthreads();
    }

    // ---- finalize: quad-reduce l, O /= l, tf32-round, write [b][n][h*32+d] ----
    int b = bh >> 3, h = bh & 7;
    size_t base = (size_t)b * SEQ * 256 + h * HD;
#pragma unroll
    for (int mt = 0; mt < 2; mt++) {
        float l0 = l_i[mt][0], l1 = l_i[mt][1];
        l0 += __shfl_xor_sync(0xffffffffu, l0, 1);
        l0 += __shfl_xor_sync(0xffffffffu, l0, 2);
        l1 += __shfl_xor_sync(0xffffffffu, l1, 1);
        l1 += __shfl_xor_sync(0xffffffffu, l1, 2);
        float inv0 = 1.f / l0, inv1 = 1.f / l1;
        int rowa = q0 + warp*32 + mt*16 + g;
#pragma unroll
        for (int nt = 0; nt < 4; nt++) {
            int d = nt*8 + 2*tg;
            g_o[base + (size_t)rowa       * 256 + d    ] = to_tf32(o[mt][nt][0] * inv0);
            g_o[base + (size_t)rowa       * 256 + d + 1] = to_tf32(o[mt][nt][1] * inv0);
            g_o[base + (size_t)(rowa + 8) * 256 + d    ] = to_tf32(o[mt][nt][2] * inv1);
            g_o[base + (size_t)(rowa + 8) * 256 + d + 1] = to_tf32(o[mt][nt][3] * inv1);
        }
    }
}

// ---------------------------------------------------------------------------
extern "C" void kernel_launch(void* const* d_in, const int* in_sizes, int n_in,
                              void* d_out, int out_size)
{
    const float* x      = (const float*)d_in[0];
    const float* w_qkv  = (const float*)d_in[1];
    const float* b_qkv  = (const float*)d_in[2];
    const float* w_proj = (const float*)d_in[3];
    const float* b_proj = (const float*)d_in[4];
    // d_in[5] rel_bias: per-head scalar, softmax-invariant -> unused
    float* out = (float*)d_out;

    pack_x_kernel<<<(BATCH*SEQ*256/4 + 255) / 256, 256>>>(x);
    pack_w_kernel<<<(256*768 + 256*256 + 255) / 256, 256>>>(w_qkv, w_proj);
    gemm_kernel<0><<<dim3(12, 128), 128>>>(b_qkv, nullptr, 8192, 768, 256);
    attn_kernel<<<dim3(SEQ / 128, BATCH * NH), 128>>>();
    gemm_kernel<1><<<dim3(4, 128), 128>>>(b_proj, out, 8192, 256, 256);
}